// round 7
// baseline (speedup 1.0000x reference)
#include <cuda_runtime.h>

#define OC_N       32
#define TPO        144            // tables per output channel
#define IC_N       16
#define PH         34
#define PW         34
#define CH_STRIDE  (PH*PW)        // 1156
#define TILE_ELEMS (IC_N*CH_STRIDE)   // 18496 floats = 73984 B
#define NTHREADS   512
#define SB         (8*PW*4)       // 1088: byte stride between the 2 positions

typedef unsigned long long u64;

#define FMA2(d, a, b, c) \
    asm("fma.rn.f32x2 %0, %1, %2, %3;" : "=l"(d) : "l"(a), "l"(b), "l"(c))
#define PACK2(d, lo, hi) \
    asm("mov.b64 %0, {%1, %2};" : "=l"(d) : "f"(lo), "f"(hi))
#define UNPK2F(lo, hi, s) \
    asm("mov.b64 {%0, %1}, %2;" : "=f"(lo), "=f"(hi) : "l"(s))
#define UNPK2U(lo, hi, s) \
    asm("mov.b64 {%0, %1}, %2;" : "=r"(lo), "=r"(hi) : "l"(s))

// Block = (batch, oc-pair, image-half). 512 threads = 2 x 256 (one oc each),
// sharing ONE padded-image tile. Each thread: 2 positions evaluated as a
// packed f32x2 lane-pair; 144 tables; per table: 2 bcast LDS.128 + 4 LDS.32
// + 3 packed FMA.
// Per-table smem record (32B): {off0<<2, off1<<2, b, b} {c, c, d, d}.
extern __shared__ float smem[];

__global__ void __launch_bounds__(NTHREADS, 2)
lutconv_fused(const float*  __restrict__ inp,
              const float4* __restrict__ w4,
              const int*    __restrict__ mc,
              const int*    __restrict__ mkh,
              const int*    __restrict__ mkw,
              float*        __restrict__ out) {
    const int bid = blockIdx.x;
    const int b    = bid >> 5;
    const int q    = bid & 31;
    const int ocp  = q >> 1;          // oc pair (0..15)
    const int h    = q & 1;           // image half
    const int tid  = threadIdx.x;
    const int wg   = tid >> 8;        // which oc of the pair
    const int ttid = tid & 255;
    const int oc   = ocp*2 + wg;

    float*  tile  = smem;                               // [TILE_ELEMS]
    float4* srec  = (float4*)(smem + TILE_ELEMS);       // [2*TPO*2] 32B/table
    float*  scw   = (float*)(srec + 4*TPO);             // [2*TPO]
    float*  sA    = scw + 2*TPO;                        // [2]

    // --- Per-table precompute for BOTH ocs (288 tables)
    if (tid < 2*TPO) {
        const int loc = tid;
        const int oci = loc >= TPO;
        const int t   = (ocp*2 + oci)*TPO + (loc - oci*TPO);
        const float4 wv = w4[t];
        const float bco = 0.25f * (-wv.x + wv.y - wv.z + wv.w);
        const float cco = 0.25f * (-wv.x - wv.y + wv.z + wv.w);
        const float dco = 0.25f * ( wv.x - wv.y - wv.z + wv.w);
        const float aco = 0.25f * ( wv.x + wv.y + wv.z + wv.w);
        const int m0 = 2*t;
        const unsigned off0 = (unsigned)(mc[m0  ]*CH_STRIDE + mkh[m0  ]*PW + mkw[m0  ]) << 2;
        const unsigned off1 = (unsigned)(mc[m0+1]*CH_STRIDE + mkh[m0+1]*PW + mkw[m0+1]) << 2;
        float4 r0, r1;
        r0.x = __uint_as_float(off0); r0.y = __uint_as_float(off1);
        r0.z = bco; r0.w = bco;
        r1.x = cco; r1.y = cco; r1.z = dco; r1.w = dco;
        srec[2*loc    ] = r0;
        srec[2*loc + 1] = r1;
        scw[loc] = aco;
    }

    // --- Stage padded tile: vector zero-fill + float4 interior copy
    {
        const float4 z4 = make_float4(0.f, 0.f, 0.f, 0.f);
        float4* t4 = (float4*)tile;
        #pragma unroll
        for (int i = tid; i < TILE_ELEMS/4; i += NTHREADS) t4[i] = z4;
    }
    __syncthreads();
    {
        const float4* ib4 = (const float4*)(inp + (size_t)b * (IC_N*32*32));
        #pragma unroll
        for (int i = tid; i < 4096; i += NTHREADS) {    // 8 iterations
            const float4 v = ib4[i];
            const int j = i << 2;
            const int c = j >> 10;
            const int y = (j >> 5) & 31;
            const int x = j & 31;
            float* dst = tile + c*CH_STRIDE + (y+1)*PW + x + 1;
            dst[0] = v.x; dst[1] = v.y; dst[2] = v.z; dst[3] = v.w;
        }
    }
    __syncthreads();

    // --- Per-oc constant term
    if (ttid < 32) {
        const float* w_ = scw + wg*TPO;
        float s = w_[ttid] + w_[ttid+32] + w_[ttid+64] + w_[ttid+96]
                + (ttid < (TPO - 128) ? w_[ttid+128] : 0.0f);
        #pragma unroll
        for (int d = 16; d; d >>= 1) s += __shfl_xor_sync(0xffffffffu, s, d);
        if (ttid == 0) sA[wg] = s;
    }
    __syncthreads();

    // --- Main loop (packed f32x2): positions y = h*16 + ttid/32 and +8
    u64 acc; PACK2(acc, 0.0f, 0.0f);
    const char* base = (const char*)(tile + (h*16 + (ttid >> 5))*PW + (ttid & 31));
    const ulonglong2* cf = (const ulonglong2*)srec + wg*(2*TPO);

    #pragma unroll 2
    for (int t = 0; t < TPO; ++t) {
        const ulonglong2 u0 = cf[2*t];      // {off0|off1, bb}
        const ulonglong2 u1 = cf[2*t + 1];  // {cc, dd}
        unsigned off0, off1;
        UNPK2U(off0, off1, u0.x);
        const char* p0 = base + off0;
        const char* p1 = base + off1;
        const float x0a = *(const float*)(p0);
        const float x0b = *(const float*)(p0 + SB);
        const float x1a = *(const float*)(p1);
        const float x1b = *(const float*)(p1 + SB);
        u64 x0p, x1p;
        PACK2(x0p, x0a, x0b);
        PACK2(x1p, x1a, x1b);
        u64 t1;
        FMA2(t1, u1.y, x1p, u0.y);          // d*x1 + b
        FMA2(acc, x0p, t1, acc);            // += x0*(b + d*x1)
        FMA2(acc, u1.x, x1p, acc);          // += c*x1
    }

    float r0, r1;
    UNPK2F(r0, r1, acc);
    const float A = sA[wg];
    float* ob = out + ((size_t)(b*OC_N + oc)) * 1024 + h*512;
    ob[ttid      ] = r0 + A;
    ob[ttid + 256] = r1 + A;
}

// ---------------------------------------------------------------------------
extern "C" void kernel_launch(void* const* d_in, const int* in_sizes, int n_in,
                              void* d_out, int out_size) {
    const float*  inp = (const float*)d_in[0];
    const float4* w4  = (const float4*)d_in[1];
    const int*    mc  = (const int*)d_in[2];
    const int*    mkh = (const int*)d_in[3];
    const int*    mkw = (const int*)d_in[4];
    float*        out = (float*)d_out;

    const int smem_bytes = TILE_ELEMS*(int)sizeof(float)     // 73984
                         + 4*TPO*(int)sizeof(float4)         // 9216
                         + 2*TPO*(int)sizeof(float)          // 1152
                         + 2*(int)sizeof(float);             // -> 84360 B
    cudaFuncSetAttribute(lutconv_fused,
                         cudaFuncAttributeMaxDynamicSharedMemorySize, smem_bytes);
    lutconv_fused<<<256, NTHREADS, smem_bytes>>>(inp, w4, mc, mkh, mkw, out);
}

// round 8
// speedup vs baseline: 2.1015x; 2.1015x over previous
#include <cuda_runtime.h>
#include <cuda_fp16.h>

#define OC_N       32
#define TPO        144              // tables per output channel
#define IC_N       16
#define PH         34
#define PW         34
#define CH_STRIDE  (PH*PW)          // 1156
#define TILE_ELEMS (IC_N*CH_STRIDE) // 18496 elements
#define NTHREADS   512

// Block = (batch, oc). 512 threads; thread handles 2 x-adjacent positions as
// one half2 lane-pair. Tile in fp16, TWO parity copies (B shifted by one
// element) so every pair load is a 4B-aligned LDS.32.
// Per-table record (ONE 16B broadcast): {off0E|off1E<<16, bb, cc, dd} where
// offE is an even element offset into the combined 2-copy tile.
extern __shared__ float smem[];

__global__ void __launch_bounds__(NTHREADS, 2)
lutconv_fused(const float*  __restrict__ inp,
              const float4* __restrict__ w4,
              const int*    __restrict__ mc,
              const int*    __restrict__ mkh,
              const int*    __restrict__ mkw,
              float*        __restrict__ out) {
    const int b   = blockIdx.x >> 5;
    const int oc  = blockIdx.x & 31;
    const int tid = threadIdx.x;

    __half* ht    = (__half*)smem;                      // [2*TILE_ELEMS] A then B
    float4* srec  = (float4*)(smem + TILE_ELEMS);       // reuse layout: after 73984B
    float*  scw   = (float*)(srec + TPO);               // [TPO]
    float*  sA    = scw + TPO;                          // [1]

    // --- Per-table precompute for this oc (144 tables)
    if (tid < TPO) {
        const int t = oc*TPO + tid;
        const float4 wv = w4[t];
        const float bco = 0.25f * (-wv.x + wv.y - wv.z + wv.w);
        const float cco = 0.25f * (-wv.x - wv.y + wv.z + wv.w);
        const float dco = 0.25f * ( wv.x - wv.y - wv.z + wv.w);
        const float aco = 0.25f * ( wv.x + wv.y + wv.z + wv.w);
        const int m0 = 2*t;
        unsigned o0 = (unsigned)(mc[m0  ]*CH_STRIDE + mkh[m0  ]*PW + mkw[m0  ]);
        unsigned o1 = (unsigned)(mc[m0+1]*CH_STRIDE + mkh[m0+1]*PW + mkw[m0+1]);
        // fold parity: odd offsets read from copy B (shifted by one element)
        o0 = (o0 & 1u) ? (unsigned)(TILE_ELEMS) + o0 - 1u : o0;
        o1 = (o1 & 1u) ? (unsigned)(TILE_ELEMS) + o1 - 1u : o1;
        const __half2 bb = __float2half2_rn(bco);
        const __half2 cc = __float2half2_rn(cco);
        const __half2 dd = __float2half2_rn(dco);
        float4 p;
        p.x = __uint_as_float(o0 | (o1 << 16));
        p.y = *(const float*)&bb;
        p.z = *(const float*)&cc;
        p.w = *(const float*)&dd;
        srec[tid] = p;
        scw[tid]  = aco;
    }

    // --- Zero both fp16 tile copies (73984 B) vectorized
    {
        const float4 z4 = make_float4(0.f, 0.f, 0.f, 0.f);
        float4* t4 = (float4*)ht;
        #pragma unroll
        for (int i = tid; i < (2*TILE_ELEMS*2)/16; i += NTHREADS) t4[i] = z4;
    }
    __syncthreads();

    // --- Stage interior: f32 -> f16, write copy A at e and copy B at e-1
    {
        const float4* ib4 = (const float4*)(inp + (size_t)b * (IC_N*32*32));
        #pragma unroll
        for (int i = tid; i < 4096; i += NTHREADS) {    // 8 iterations
            const float4 v = ib4[i];
            const int j = i << 2;
            const int c = j >> 10;
            const int y = (j >> 5) & 31;
            const int x = j & 31;
            const int e = c*CH_STRIDE + (y+1)*PW + (x+1);
            const __half h0 = __float2half(v.x);
            const __half h1 = __float2half(v.y);
            const __half h2 = __float2half(v.z);
            const __half h3 = __float2half(v.w);
            ht[e  ] = h0; ht[e+1] = h1; ht[e+2] = h2; ht[e+3] = h3;
            ht[TILE_ELEMS + e-1] = h0; ht[TILE_ELEMS + e  ] = h1;
            ht[TILE_ELEMS + e+1] = h2; ht[TILE_ELEMS + e+2] = h3;
        }
    }
    __syncthreads();

    // --- Per-oc constant term
    if (tid < 32) {
        float s = scw[tid] + scw[tid+32] + scw[tid+64] + scw[tid+96]
                + (tid < (TPO - 128) ? scw[tid+128] : 0.0f);
        #pragma unroll
        for (int d = 16; d; d >>= 1) s += __shfl_xor_sync(0xffffffffu, s, d);
        if (tid == 0) *sA = s;
    }
    __syncthreads();

    // --- Main loop.
    // lane l (0..31): rows split 16 apart for conflict-free dual-row warps:
    //   row = (l>>4)*16 + warp, xp = l&15; positions (row, 2xp) and (row, 2xp+1)
    const int l    = tid & 31;
    const int wrp  = tid >> 5;            // 0..15
    const int row  = ((l >> 4) << 4) + wrp;
    const int xp   = l & 15;
    const char* tb = (const char*)ht + (row*PW + 2*xp)*2;

    float acc0 = 0.f, acc1 = 0.f;

    #pragma unroll 2
    for (int t = 0; t < TPO; t += 2) {
        const float4 pa = srec[t];
        const float4 pb = srec[t+1];
        const unsigned ua = __float_as_uint(pa.x);
        const unsigned ub = __float_as_uint(pb.x);
        const __half2 xa0 = *(const __half2*)(tb + (ua & 0xffffu)*2u);
        const __half2 xa1 = *(const __half2*)(tb + (ua >> 16)*2u);
        const __half2 xb0 = *(const __half2*)(tb + (ub & 0xffffu)*2u);
        const __half2 xb1 = *(const __half2*)(tb + (ub >> 16)*2u);

        const __half2 ba = *(const __half2*)&pa.y;
        const __half2 ca = *(const __half2*)&pa.z;
        const __half2 da = *(const __half2*)&pa.w;
        const __half2 bb = *(const __half2*)&pb.y;
        const __half2 cb = *(const __half2*)&pb.z;
        const __half2 db = *(const __half2*)&pb.w;

        const __half2 t1a = __hfma2(da, xa1, ba);
        const __half2 sa  = __hfma2(xa0, t1a, __hmul2(ca, xa1));
        const __half2 t1b = __hfma2(db, xb1, bb);
        const __half2 sb  = __hfma2(xb0, t1b, __hmul2(cb, xb1));

        const float2 fa = __half22float2(sa);
        const float2 fb = __half22float2(sb);
        acc0 += fa.x; acc1 += fa.y;
        acc0 += fb.x; acc1 += fb.y;
    }

    const float A = *sA;
    float2 r; r.x = acc0 + A; r.y = acc1 + A;
    float* ob = out + ((size_t)(b*OC_N + oc)) * 1024 + row*32 + 2*xp;
    *(float2*)ob = r;
}

// ---------------------------------------------------------------------------
extern "C" void kernel_launch(void* const* d_in, const int* in_sizes, int n_in,
                              void* d_out, int out_size) {
    const float*  inp = (const float*)d_in[0];
    const float4* w4  = (const float4*)d_in[1];
    const int*    mc  = (const int*)d_in[2];
    const int*    mkh = (const int*)d_in[3];
    const int*    mkw = (const int*)d_in[4];
    float*        out = (float*)d_out;

    const int smem_bytes = 2*TILE_ELEMS*(int)sizeof(__half)  // 73984 (two fp16 copies)
                         + TPO*(int)sizeof(float4)           // 2304
                         + (TPO + 1)*(int)sizeof(float);     // 580  -> 76868 B
    cudaFuncSetAttribute(lutconv_fused,
                         cudaFuncAttributeMaxDynamicSharedMemorySize, smem_bytes);
    lutconv_fused<<<8*OC_N, NTHREADS, smem_bytes>>>(inp, w4, mc, mkh, mkw, out);
}

// round 9
// speedup vs baseline: 2.3215x; 1.1047x over previous
#include <cuda_runtime.h>
#include <cuda_fp16.h>

#define OC_N       32
#define TPO        144              // tables per output channel
#define IC_N       16
#define PH         34
#define PW         34
#define CH_STRIDE  (PH*PW)          // 1156
#define TILE_ELEMS (IC_N*CH_STRIDE) // 18496 elements
#define NTHREADS   256
#define ROWOFF     (8*PW*2)         // 544 B: +8 rows (LDS immediate offset)

// Block = (batch, oc), 256 threads. Each thread evaluates 4 positions:
// half2 pair (row, x..x+1) and pair (row+8, x..x+1); the +8-row loads use an
// LDS immediate offset on the same addresses. Tile in fp16 with TWO parity
// copies so every pair load is one aligned LDS.32.
// Per-table record (ONE 16B broadcast): {off0E|off1E<<16, bb, cc, dd}.
extern __shared__ float smem[];

__global__ void __launch_bounds__(NTHREADS, 2)
lutconv_fused(const float*  __restrict__ inp,
              const float4* __restrict__ w4,
              const int*    __restrict__ mc,
              const int*    __restrict__ mkh,
              const int*    __restrict__ mkw,
              float*        __restrict__ out) {
    const int b   = blockIdx.x >> 5;
    const int oc  = blockIdx.x & 31;
    const int tid = threadIdx.x;

    __half* ht    = (__half*)smem;                      // [2*TILE_ELEMS]
    float4* srec  = (float4*)(smem + TILE_ELEMS);       // [TPO] (after 73984 B)
    float*  scw   = (float*)(srec + TPO);               // [TPO]
    float*  sA    = scw + TPO;                          // [1]

    // --- Per-table precompute
    if (tid < TPO) {
        const int t = oc*TPO + tid;
        const float4 wv = w4[t];
        const float bco = 0.25f * (-wv.x + wv.y - wv.z + wv.w);
        const float cco = 0.25f * (-wv.x - wv.y + wv.z + wv.w);
        const float dco = 0.25f * ( wv.x - wv.y - wv.z + wv.w);
        const float aco = 0.25f * ( wv.x + wv.y + wv.z + wv.w);
        const int m0 = 2*t;
        unsigned o0 = (unsigned)(mc[m0  ]*CH_STRIDE + mkh[m0  ]*PW + mkw[m0  ]);
        unsigned o1 = (unsigned)(mc[m0+1]*CH_STRIDE + mkh[m0+1]*PW + mkw[m0+1]);
        o0 = (o0 & 1u) ? (unsigned)TILE_ELEMS + o0 - 1u : o0;   // odd -> copy B
        o1 = (o1 & 1u) ? (unsigned)TILE_ELEMS + o1 - 1u : o1;
        const __half2 bb = __float2half2_rn(bco);
        const __half2 cc = __float2half2_rn(cco);
        const __half2 dd = __float2half2_rn(dco);
        float4 p;
        p.x = __uint_as_float(o0 | (o1 << 16));
        p.y = *(const float*)&bb;
        p.z = *(const float*)&cc;
        p.w = *(const float*)&dd;
        srec[tid] = p;
        scw[tid]  = aco;
    }

    // --- Zero both fp16 tile copies (73984 B)
    {
        const float4 z4 = make_float4(0.f, 0.f, 0.f, 0.f);
        float4* t4 = (float4*)ht;
        #pragma unroll
        for (int i = tid; i < (2*TILE_ELEMS*2)/16; i += NTHREADS) t4[i] = z4;
    }
    __syncthreads();

    // --- Stage interior: f32 -> f16, copy A at e, copy B at e-1
    {
        const float4* ib4 = (const float4*)(inp + (size_t)b * (IC_N*32*32));
        #pragma unroll
        for (int i = tid; i < 4096; i += NTHREADS) {    // 16 iterations
            const float4 v = ib4[i];
            const int j = i << 2;
            const int c = j >> 10;
            const int y = (j >> 5) & 31;
            const int x = j & 31;
            const int e = c*CH_STRIDE + (y+1)*PW + (x+1);
            const __half h0 = __float2half(v.x);
            const __half h1 = __float2half(v.y);
            const __half h2 = __float2half(v.z);
            const __half h3 = __float2half(v.w);
            ht[e  ] = h0; ht[e+1] = h1; ht[e+2] = h2; ht[e+3] = h3;
            ht[TILE_ELEMS + e-1] = h0; ht[TILE_ELEMS + e  ] = h1;
            ht[TILE_ELEMS + e+1] = h2; ht[TILE_ELEMS + e+2] = h3;
        }
    }
    __syncthreads();

    // --- Per-oc constant term
    if (tid < 32) {
        float s = scw[tid] + scw[tid+32] + scw[tid+64] + scw[tid+96]
                + (tid < (TPO - 128) ? scw[tid+128] : 0.0f);
        #pragma unroll
        for (int d = 16; d; d >>= 1) s += __shfl_xor_sync(0xffffffffu, s, d);
        if (tid == 0) *sA = s;
    }
    __syncthreads();

    // --- Main loop: 4 positions/thread.
    // lanes 0-15: row = wrp, lanes 16-31: row = wrp+16 (conflict-free);
    // each also handles row+8 via +544B immediate. x-pair = 2*(l&15).
    const int l    = tid & 31;
    const int wrp  = tid >> 5;                     // 0..7
    const int rowA = wrp + ((l >> 4) << 4);        // wrp or wrp+16
    const int x    = (l & 15) << 1;
    const char* tb = (const char*)ht + (rowA*PW + x)*2;

    float f00 = 0.f, f01 = 0.f, f10 = 0.f, f11 = 0.f;

    #pragma unroll 2
    for (int t = 0; t < TPO; t += 2) {
        const float4 pa = srec[t];
        const float4 pb = srec[t+1];
        const unsigned ua = __float_as_uint(pa.x);
        const unsigned ub = __float_as_uint(pb.x);
        const char* a0 = tb + (ua & 0xffffu)*2u;
        const char* a1 = tb + (ua >> 16)*2u;
        const char* b0 = tb + (ub & 0xffffu)*2u;
        const char* b1 = tb + (ub >> 16)*2u;

        const __half2 xa0 = *(const __half2*)(a0);
        const __half2 xa1 = *(const __half2*)(a1);
        const __half2 ya0 = *(const __half2*)(a0 + ROWOFF);
        const __half2 ya1 = *(const __half2*)(a1 + ROWOFF);
        const __half2 xb0 = *(const __half2*)(b0);
        const __half2 xb1 = *(const __half2*)(b1);
        const __half2 yb0 = *(const __half2*)(b0 + ROWOFF);
        const __half2 yb1 = *(const __half2*)(b1 + ROWOFF);

        const __half2 Ba = *(const __half2*)&pa.y;
        const __half2 Ca = *(const __half2*)&pa.z;
        const __half2 Da = *(const __half2*)&pa.w;
        const __half2 Bb = *(const __half2*)&pb.y;
        const __half2 Cb = *(const __half2*)&pb.z;
        const __half2 Db = *(const __half2*)&pb.w;

        // rows rowA (pair 01): 2-table half2 accumulation, then fp32 flush
        __half2 acc01 = __hmul2(Ca, xa1);
        acc01 = __hfma2(xa0, __hfma2(Da, xa1, Ba), acc01);
        acc01 = __hfma2(Cb, xb1, acc01);
        acc01 = __hfma2(xb0, __hfma2(Db, xb1, Bb), acc01);
        // rows rowA+8 (pair 23)
        __half2 acc23 = __hmul2(Ca, ya1);
        acc23 = __hfma2(ya0, __hfma2(Da, ya1, Ba), acc23);
        acc23 = __hfma2(Cb, yb1, acc23);
        acc23 = __hfma2(yb0, __hfma2(Db, yb1, Bb), acc23);

        const float2 fa = __half22float2(acc01);
        f00 += fa.x; f01 += fa.y;
        const float2 fb = __half22float2(acc23);
        f10 += fb.x; f11 += fb.y;
    }

    const float A = *sA;
    float* ob = out + ((size_t)(b*OC_N + oc)) * 1024;
    float2 r0; r0.x = f00 + A; r0.y = f01 + A;
    float2 r1; r1.x = f10 + A; r1.y = f11 + A;
    *(float2*)(ob + rowA*32 + x)       = r0;
    *(float2*)(ob + (rowA+8)*32 + x)   = r1;
}

// ---------------------------------------------------------------------------
extern "C" void kernel_launch(void* const* d_in, const int* in_sizes, int n_in,
                              void* d_out, int out_size) {
    const float*  inp = (const float*)d_in[0];
    const float4* w4  = (const float4*)d_in[1];
    const int*    mc  = (const int*)d_in[2];
    const int*    mkh = (const int*)d_in[3];
    const int*    mkw = (const int*)d_in[4];
    float*        out = (float*)d_out;

    const int smem_bytes = 2*TILE_ELEMS*(int)sizeof(__half)  // 73984
                         + TPO*(int)sizeof(float4)           // 2304
                         + (TPO + 1)*(int)sizeof(float);     // 580 -> 76868 B
    cudaFuncSetAttribute(lutconv_fused,
                         cudaFuncAttributeMaxDynamicSharedMemorySize, smem_bytes);
    lutconv_fused<<<8*OC_N, NTHREADS, smem_bytes>>>(inp, w4, mc, mkh, mkw, out);
}